// round 5
// baseline (speedup 1.0000x reference)
#include <cuda_runtime.h>
#include <cuda_bf16.h>
#include <cstdint>

// ---------------------------------------------------------------------------
//   y   = W @ x + b   (oc=128, cin=128, vox=186624)
//   out = leaky_0.2( y * (y + att[c,l,pp]/nz[c,l] + 1) )
// GEMM on mma.sync m16n8k16 (bf16) via 3-way split: Wh*xh + Wh*xl + Wl*xh
// R5: 2 CTAs/SM (TILE_V=96, 384 thr, 112KB smem) for phase overlap.
// ---------------------------------------------------------------------------

#define CIN    128
#define COUT   128
#define HWDIM  5184
#define NVOX   186624
#define PATCH  9
#define PPSQ   81
#define NW     576
#define LPATCH 2304

#define TILE_V  96
#define THREADS 384

// dynamic smem (bytes): xh[96][128]bf16 (24KB), xl (24KB), Wh+Wl (64KB)
#define SM_XH 0
#define SM_XL 24576
#define SM_W  49152
#define SMEM_TOTAL 114688   // 112KB -> 2 CTAs/SM

__device__ float g_invnz[COUT * LPATCH];                // 1/(nnz + 1e-5)
__device__ __align__(16) unsigned short g_Wsw[32768];   // [Wh 32KB][Wl 32KB], swizzled

// ---------------------------------------------------------------------------
// helpers
// ---------------------------------------------------------------------------
__device__ __forceinline__ uint32_t smem_u32(const void* p) {
    uint32_t a;
    asm("{ .reg .u64 t; cvta.to.shared.u64 t, %1; cvt.u32.u64 %0, t; }"
        : "=r"(a) : "l"(p));
    return a;
}
__device__ __forceinline__ uint32_t pack_bf16x2(float lo, float hi) {
    uint32_t r;
    asm("cvt.rn.bf16x2.f32 %0, %1, %2;" : "=r"(r) : "f"(hi), "f"(lo));
    return r;
}
__device__ __forceinline__ int redux_add(int v) {
    int r;
    asm("redux.sync.add.s32 %0, %1, 0xffffffff;" : "=r"(r) : "r"(v));
    return r;
}
__device__ __forceinline__ void sts64(uint32_t addr, uint32_t a, uint32_t b) {
    asm volatile("st.shared.v2.u32 [%0], {%1, %2};"
                 :: "r"(addr), "r"(a), "r"(b) : "memory");
}
__device__ __forceinline__ void ldsm_x4(uint32_t addr, uint32_t* r) {
    asm volatile("ldmatrix.sync.aligned.m8n8.x4.shared.b16 {%0,%1,%2,%3}, [%4];"
                 : "=r"(r[0]), "=r"(r[1]), "=r"(r[2]), "=r"(r[3]) : "r"(addr));
}
__device__ __forceinline__ void mma16816(float* d, const uint32_t* a,
                                         uint32_t b0, uint32_t b1) {
    asm volatile(
        "mma.sync.aligned.m16n8k16.row.col.f32.bf16.bf16.f32 "
        "{%0,%1,%2,%3}, {%4,%5,%6,%7}, {%8,%9}, {%0,%1,%2,%3};"
        : "+f"(d[0]), "+f"(d[1]), "+f"(d[2]), "+f"(d[3])
        : "r"(a[0]), "r"(a[1]), "r"(a[2]), "r"(a[3]), "r"(b0), "r"(b1));
}
// swizzled byte offset in a [row][k] bf16 tile, 256B rows, 16B-chunk xor
__device__ __forceinline__ uint32_t swz(int row, uint32_t kbyte) {
    return (uint32_t)row * 256u + (kbyte ^ (uint32_t)((row & 7) << 4));
}

// ---------------------------------------------------------------------------
// Prep: W bf16 hi/lo split (swizzled) + invnz, warp per 4 rows via float4.
// 9216 CTAs x 256 thr: 8 warps x 4 rows = 32 rows/CTA; 294912 rows total.
// ---------------------------------------------------------------------------
__global__ __launch_bounds__(256) void prep_kernel(const float* __restrict__ att,
                                                   const float* __restrict__ W)
{
    const int tid = threadIdx.x;
    const int blk = blockIdx.x;

    if (blk < 64) {   // W split: 16384 elements
        int idx = blk * 256 + tid;
        int oc = idx >> 7, k = idx & 127;
        float w = W[idx];
        __nv_bfloat16 h = __float2bfloat16(w);
        float hf = __bfloat162float(h);
        __nv_bfloat16 l = __float2bfloat16(w - hf);
        uint32_t off = swz(oc, (uint32_t)(k * 2)) >> 1;
        g_Wsw[off]         = *(unsigned short*)&h;
        g_Wsw[off + 16384] = *(unsigned short*)&l;
    }

    // warp handles att rows [g*4, g*4+4): 324 floats = 81 aligned float4
    const int g = (blk * 256 + tid) >> 5;
    const int lane = tid & 31;
    const float4* a4 = (const float4*)att + (size_t)g * 81;

    int c0 = 0, c1 = 0, c2 = 0, c3 = 0;
#pragma unroll
    for (int p = 0; p < 3; p++) {
        int idx = p * 32 + lane;
        if (idx < 81) {
            float4 f = __ldg(&a4[idx]);
            int e = idx * 4;
            int r0 = (e >= 81) + (e >= 162) + (e >= 243);
            int r3 = (e + 3 >= 81) + (e + 3 >= 162) + (e + 3 >= 243);
            if (r0 == r3) {
                int cnt = (f.x != 0.f) + (f.y != 0.f) + (f.z != 0.f) + (f.w != 0.f);
                c0 += (r0 == 0) ? cnt : 0;
                c1 += (r0 == 1) ? cnt : 0;
                c2 += (r0 == 2) ? cnt : 0;
                c3 += (r0 == 3) ? cnt : 0;
            } else {
                float vv[4] = { f.x, f.y, f.z, f.w };
#pragma unroll
                for (int j = 0; j < 4; j++) {
                    int ej = e + j;
                    int rj = (ej >= 81) + (ej >= 162) + (ej >= 243);
                    int nz = (vv[j] != 0.f);
                    c0 += (rj == 0) ? nz : 0;
                    c1 += (rj == 1) ? nz : 0;
                    c2 += (rj == 2) ? nz : 0;
                    c3 += (rj == 3) ? nz : 0;
                }
            }
        }
    }
    c0 = redux_add(c0); c1 = redux_add(c1);
    c2 = redux_add(c2); c3 = redux_add(c3);
    if (lane < 4) {
        int c = (lane == 0) ? c0 : (lane == 1) ? c1 : (lane == 2) ? c2 : c3;
        g_invnz[g * 4 + lane] = 1.0f / ((float)c + 1e-5f);
    }
}

// ---------------------------------------------------------------------------
// Fused kernel: 128 oc x 96 vox per CTA, 2 CTAs/SM.
//   12 warps: ocg = wid&3 (32 oc), voxg = wid>>2 (0..2, 32 vox each).
// ---------------------------------------------------------------------------
__global__ __launch_bounds__(THREADS, 2)
void fused_kernel(const float* __restrict__ x,
                  const float* __restrict__ att,
                  const float* __restrict__ b,
                  float* __restrict__ out)
{
    extern __shared__ __align__(16) char smem[];
    const uint32_t sbase = smem_u32(smem);
    const int tid  = threadIdx.x;
    const int lane = tid & 31;
    const int wid  = tid >> 5;
    const int v0   = blockIdx.x * TILE_V;

    // --- copy pre-swizzled Wh/Wl (64KB) to smem ---
    {
        const float4* Wv = (const float4*)g_Wsw;
        float4* sWv = (float4*)(smem + SM_W);
        for (int i = tid; i < 4096; i += THREADS)
            sWv[i] = Wv[i];
    }

    // --- load x tile (fp32, coalesced) -> bf16 hi/lo -> swizzled smem ---
    {
        const int vt = tid % 96;
        const int kh = tid / 96;              // 0..3 (uniform per warp)
        const float* xp = x + (size_t)v0 + vt;
        const uint32_t rowbase = (uint32_t)vt * 256u;
        const uint32_t swm = (uint32_t)((vt & 7) << 4);
#pragma unroll 4
        for (int it = 0; it < 8; it++) {
            int k0 = kh * 4 + it * 16;        // 4 consecutive k per sts64
            float f0 = xp[(size_t)(k0 + 0) * NVOX];
            float f1 = xp[(size_t)(k0 + 1) * NVOX];
            float f2 = xp[(size_t)(k0 + 2) * NVOX];
            float f3 = xp[(size_t)(k0 + 3) * NVOX];
            uint32_t h01 = pack_bf16x2(f0, f1);
            uint32_t h23 = pack_bf16x2(f2, f3);
            float h0 = __uint_as_float(h01 << 16);
            float h1 = __uint_as_float(h01 & 0xffff0000u);
            float h2 = __uint_as_float(h23 << 16);
            float h3 = __uint_as_float(h23 & 0xffff0000u);
            uint32_t l01 = pack_bf16x2(f0 - h0, f1 - h1);
            uint32_t l23 = pack_bf16x2(f2 - h2, f3 - h3);
            uint32_t off = rowbase + (((uint32_t)(k0 * 2)) ^ swm);
            sts64(sbase + SM_XH + off, h01, h23);
            sts64(sbase + SM_XL + off, l01, l23);
        }
    }
    __syncthreads();

    // --- accumulators, init with bias ---
    const int ocb = (wid & 3) * 32;
    const int vh  = (wid >> 2) * 32;
    const int ocl = ocb + (lane >> 2);

    float acc[2][4][4];
#pragma unroll
    for (int t = 0; t < 2; t++) {
        float b0 = __ldg(b + ocl + 16 * t);
        float b1 = __ldg(b + ocl + 16 * t + 8);
#pragma unroll
        for (int nb = 0; nb < 4; nb++) {
            acc[t][nb][0] = b0; acc[t][nb][1] = b0;
            acc[t][nb][2] = b1; acc[t][nb][3] = b1;
        }
    }

    // --- ldmatrix lane addressing (same mapping as R4, verified) ---
    const int aRow = ocb + (lane & 15);
    const uint32_t aSw = (uint32_t)((aRow & 7) << 4);
    const uint32_t aK  = (uint32_t)((lane >> 4) * 16);
    const uint32_t aB  = sbase + SM_W + (uint32_t)aRow * 256u;

    const int bRow = (lane & 7) + ((lane >> 4) & 1) * 8;
    const uint32_t bSw = (uint32_t)((bRow & 7) << 4);
    const uint32_t bK  = (uint32_t)(((lane >> 3) & 1) * 16);
    uint32_t bB[2];
#pragma unroll
    for (int nbp = 0; nbp < 2; nbp++)
        bB[nbp] = sbase + (uint32_t)(vh + nbp * 16 + bRow) * 256u;

    // --- main GEMM: 8 k-steps of k16, 3 terms ---
#pragma unroll
    for (int ks = 0; ks < 8; ks++) {
        const uint32_t kbA = ((uint32_t)(ks * 32) + aK) ^ aSw;
        uint32_t a0h[4], a1h[4], a0l[4], a1l[4];
        ldsm_x4(aB + kbA,                a0h);
        ldsm_x4(aB + 4096 + kbA,         a1h);
        ldsm_x4(aB + 32768 + kbA,        a0l);
        ldsm_x4(aB + 32768 + 4096 + kbA, a1l);

        const uint32_t kbB = ((uint32_t)(ks * 32) + bK) ^ bSw;
#pragma unroll
        for (int nbp = 0; nbp < 2; nbp++) {
            uint32_t bh[4], bl[4];
            ldsm_x4(bB[nbp] + SM_XH + kbB, bh);
            ldsm_x4(bB[nbp] + SM_XL + kbB, bl);
            mma16816(acc[0][2 * nbp],     a0h, bh[0], bh[1]);
            mma16816(acc[1][2 * nbp],     a1h, bh[0], bh[1]);
            mma16816(acc[0][2 * nbp],     a0h, bl[0], bl[1]);
            mma16816(acc[1][2 * nbp],     a1h, bl[0], bl[1]);
            mma16816(acc[0][2 * nbp],     a0l, bh[0], bh[1]);
            mma16816(acc[1][2 * nbp],     a1l, bh[0], bh[1]);
            mma16816(acc[0][2 * nbp + 1], a0h, bh[2], bh[3]);
            mma16816(acc[1][2 * nbp + 1], a1h, bh[2], bh[3]);
            mma16816(acc[0][2 * nbp + 1], a0h, bl[2], bl[3]);
            mma16816(acc[1][2 * nbp + 1], a1h, bl[2], bl[3]);
            mma16816(acc[0][2 * nbp + 1], a0l, bh[2], bh[3]);
            mma16816(acc[1][2 * nbp + 1], a1l, bh[2], bh[3]);
        }
    }

    // --- epilogue from C fragments (pairs = 2 consecutive voxels) ---
    const int voxbase = v0 + vh + 2 * (lane & 3);
#pragma unroll
    for (int t = 0; t < 2; t++) {
        const int oc0 = ocl + 16 * t;
        const int oc1 = oc0 + 8;
        const float* att0 = att + (size_t)oc0 * (LPATCH * PPSQ);
        const float* att1 = att + (size_t)oc1 * (LPATCH * PPSQ);
        const float* inz0 = g_invnz + oc0 * LPATCH;
        const float* inz1 = g_invnz + oc1 * LPATCH;
        float* o0 = out + (size_t)oc0 * NVOX;
        float* o1 = out + (size_t)oc1 * NVOX;
#pragma unroll
        for (int nb = 0; nb < 4; nb++) {
            const int v = voxbase + nb * 8;          // even; v,v+1 same d-plane
            int d  = v / HWDIM;
            int hw = v - d * HWDIM;
            int id = d / PATCH,  pd = d  - id * PATCH;
            int iw = hw / PATCH, pw = hw - iw * PATCH;
            int l0 = id * NW + iw, p0 = pd * PATCH + pw;
            int l1, p1;
            if (pw == PATCH - 1) { l1 = l0 + 1; p1 = pd * PATCH; }
            else                 { l1 = l0;     p1 = p0 + 1; }

            float a00 = att0[(size_t)l0 * PPSQ + p0] * inz0[l0];
            float a01 = att0[(size_t)l1 * PPSQ + p1] * inz0[l1];
            float a10 = att1[(size_t)l0 * PPSQ + p0] * inz1[l0];
            float a11 = att1[(size_t)l1 * PPSQ + p1] * inz1[l1];

            float y;
            float2 r;
            y = acc[t][nb][0]; r.x = y * (y + a00 + 1.0f);
            r.x = (r.x >= 0.0f) ? r.x : 0.2f * r.x;
            y = acc[t][nb][1]; r.y = y * (y + a01 + 1.0f);
            r.y = (r.y >= 0.0f) ? r.y : 0.2f * r.y;
            *(float2*)(o0 + v) = r;

            y = acc[t][nb][2]; r.x = y * (y + a10 + 1.0f);
            r.x = (r.x >= 0.0f) ? r.x : 0.2f * r.x;
            y = acc[t][nb][3]; r.y = y * (y + a11 + 1.0f);
            r.y = (r.y >= 0.0f) ? r.y : 0.2f * r.y;
            *(float2*)(o1 + v) = r;
        }
    }
}

// ---------------------------------------------------------------------------
extern "C" void kernel_launch(void* const* d_in, const int* in_sizes, int n_in,
                              void* d_out, int out_size)
{
    (void)in_sizes; (void)n_in; (void)out_size;
    const float* x   = (const float*)d_in[0];
    const float* att = (const float*)d_in[1];
    const float* W   = (const float*)d_in[2];
    const float* b   = (const float*)d_in[3];
    float* out = (float*)d_out;

    // 9216 CTAs x 8 warps x 4 rows = 294912 (c,l) rows; first 64 split W
    prep_kernel<<<9216, 256>>>(att, W);

    cudaFuncSetAttribute(fused_kernel,
                         cudaFuncAttributeMaxDynamicSharedMemorySize,
                         SMEM_TOTAL);
    fused_kernel<<<NVOX / TILE_V, THREADS, SMEM_TOTAL>>>(x, att, b, out);
}

// round 6
// speedup vs baseline: 1.2414x; 1.2414x over previous
#include <cuda_runtime.h>
#include <cuda_bf16.h>
#include <cstdint>

// ---------------------------------------------------------------------------
//   y   = W @ x + b   (oc=128, cin=128, vox=186624)
//   out = leaky_0.2( y * (y + att[c,l,pp]/nz[c,l] + 1) )
// GEMM on mma.sync m16n8k16 (bf16) via 3-way split: Wh*xh + Wh*xl + Wl*xh
// R6: persistent 148-CTA kernel, W loaded once, double-buffered x tiles,
//     float4 x loads, [k][vox] B layout + ldmatrix.trans.
// ---------------------------------------------------------------------------

#define CIN    128
#define COUT   128
#define HWDIM  5184
#define NVOX   186624
#define PATCH  9
#define PPSQ   81
#define NW     576
#define LPATCH 2304

#define TILE_V  128
#define NTILES  1458          // NVOX / TILE_V
#define GRID    148
#define THREADS 512

// dynamic smem (bytes):
//   buf0: xh[128k][128v] bf16 (32KB) + xl (32KB)   @ 0
//   buf1: same                                      @ 65536
//   W:    Wh (32KB) + Wl (32KB)                     @ 131072
#define SM_W  131072
#define SMEM_TOTAL 196608

__device__ float g_invnz[COUT * LPATCH];                // 1/(nnz + 1e-5)
__device__ __align__(16) unsigned short g_Wsw[32768];   // [Wh][Wl], swizzled

// ---------------------------------------------------------------------------
// helpers
// ---------------------------------------------------------------------------
__device__ __forceinline__ uint32_t smem_u32(const void* p) {
    uint32_t a;
    asm("{ .reg .u64 t; cvta.to.shared.u64 t, %1; cvt.u32.u64 %0, t; }"
        : "=r"(a) : "l"(p));
    return a;
}
__device__ __forceinline__ uint32_t pack_bf16x2(float lo, float hi) {
    uint32_t r;
    asm("cvt.rn.bf16x2.f32 %0, %1, %2;" : "=r"(r) : "f"(hi), "f"(lo));
    return r;
}
__device__ __forceinline__ int redux_add(int v) {
    int r;
    asm("redux.sync.add.s32 %0, %1, 0xffffffff;" : "=r"(r) : "r"(v));
    return r;
}
__device__ __forceinline__ void sts64(uint32_t addr, uint32_t a, uint32_t b) {
    asm volatile("st.shared.v2.u32 [%0], {%1, %2};"
                 :: "r"(addr), "r"(a), "r"(b) : "memory");
}
__device__ __forceinline__ void ldsm_x4(uint32_t addr, uint32_t* r) {
    asm volatile("ldmatrix.sync.aligned.m8n8.x4.shared.b16 {%0,%1,%2,%3}, [%4];"
                 : "=r"(r[0]), "=r"(r[1]), "=r"(r[2]), "=r"(r[3]) : "r"(addr));
}
__device__ __forceinline__ void ldsm_x4_t(uint32_t addr, uint32_t* r) {
    asm volatile("ldmatrix.sync.aligned.m8n8.x4.trans.shared.b16 {%0,%1,%2,%3}, [%4];"
                 : "=r"(r[0]), "=r"(r[1]), "=r"(r[2]), "=r"(r[3]) : "r"(addr));
}
__device__ __forceinline__ void mma16816(float* d, const uint32_t* a,
                                         uint32_t b0, uint32_t b1) {
    asm volatile(
        "mma.sync.aligned.m16n8k16.row.col.f32.bf16.bf16.f32 "
        "{%0,%1,%2,%3}, {%4,%5,%6,%7}, {%8,%9}, {%0,%1,%2,%3};"
        : "+f"(d[0]), "+f"(d[1]), "+f"(d[2]), "+f"(d[3])
        : "r"(a[0]), "r"(a[1]), "r"(a[2]), "r"(a[3]), "r"(b0), "r"(b1));
}
// swizzled byte offset in a 256B-row tile, 16B-chunk xor by (row&7)
__device__ __forceinline__ uint32_t swz(int row, uint32_t colbyte) {
    return (uint32_t)row * 256u + (colbyte ^ (uint32_t)((row & 7) << 4));
}

// ---------------------------------------------------------------------------
// Prep: W bf16 hi/lo split (swizzled, [oc][k]) + invnz (warp per 4 att rows).
// ---------------------------------------------------------------------------
__global__ __launch_bounds__(256) void prep_kernel(const float* __restrict__ att,
                                                   const float* __restrict__ W)
{
    const int tid = threadIdx.x;
    const int blk = blockIdx.x;

    if (blk < 64) {   // W split: 16384 elements
        int idx = blk * 256 + tid;
        int oc = idx >> 7, k = idx & 127;
        float w = W[idx];
        __nv_bfloat16 h = __float2bfloat16(w);
        float hf = __bfloat162float(h);
        __nv_bfloat16 l = __float2bfloat16(w - hf);
        uint32_t off = swz(oc, (uint32_t)(k * 2)) >> 1;
        g_Wsw[off]         = *(unsigned short*)&h;
        g_Wsw[off + 16384] = *(unsigned short*)&l;
    }

    const int g = (blk * 256 + tid) >> 5;     // att row group (4 rows)
    const int lane = tid & 31;
    const float4* a4 = (const float4*)att + (size_t)g * 81;

    int c0 = 0, c1 = 0, c2 = 0, c3 = 0;
#pragma unroll
    for (int p = 0; p < 3; p++) {
        int idx = p * 32 + lane;
        if (idx < 81) {
            float4 f = __ldg(&a4[idx]);
            int e = idx * 4;
            int r0 = (e >= 81) + (e >= 162) + (e >= 243);
            int r3 = (e + 3 >= 81) + (e + 3 >= 162) + (e + 3 >= 243);
            if (r0 == r3) {
                int cnt = (f.x != 0.f) + (f.y != 0.f) + (f.z != 0.f) + (f.w != 0.f);
                c0 += (r0 == 0) ? cnt : 0;
                c1 += (r0 == 1) ? cnt : 0;
                c2 += (r0 == 2) ? cnt : 0;
                c3 += (r0 == 3) ? cnt : 0;
            } else {
                float vv[4] = { f.x, f.y, f.z, f.w };
#pragma unroll
                for (int j = 0; j < 4; j++) {
                    int ej = e + j;
                    int rj = (ej >= 81) + (ej >= 162) + (ej >= 243);
                    int nz = (vv[j] != 0.f);
                    c0 += (rj == 0) ? nz : 0;
                    c1 += (rj == 1) ? nz : 0;
                    c2 += (rj == 2) ? nz : 0;
                    c3 += (rj == 3) ? nz : 0;
                }
            }
        }
    }
    c0 = redux_add(c0); c1 = redux_add(c1);
    c2 = redux_add(c2); c3 = redux_add(c3);
    if (lane < 4) {
        int c = (lane == 0) ? c0 : (lane == 1) ? c1 : (lane == 2) ? c2 : c3;
        g_invnz[g * 4 + lane] = 1.0f / ((float)c + 1e-5f);
    }
}

// ---------------------------------------------------------------------------
// Fused persistent kernel.
// ---------------------------------------------------------------------------
struct XFrag { float4 f[8]; };   // 8 float4 = one k-row segment per iter

__device__ __forceinline__ void ldg_tile(const float* __restrict__ x,
                                         int v0, int wid, int lane, XFrag& r)
{
    // warp w loads k rows {w, w+16, ..., w+112}; lane = vox4 index
    const float* xp = x + (size_t)wid * NVOX + v0 + lane * 4;
#pragma unroll
    for (int i = 0; i < 8; i++)
        r.f[i] = *(const float4*)(xp + (size_t)(16 * i) * NVOX);
}

__device__ __forceinline__ void sts_tile(uint32_t bufbase, int wid, int lane,
                                         const XFrag& r)
{
    // xh at bufbase, xl at bufbase + 32768; row = k, col = vox*2 bytes
    const uint32_t colsw = ((uint32_t)(lane * 8)) ^ ((uint32_t)((wid & 7) << 4));
#pragma unroll
    for (int i = 0; i < 8; i++) {
        const int k = wid + 16 * i;
        float4 f = r.f[i];
        uint32_t h01 = pack_bf16x2(f.x, f.y);
        uint32_t h23 = pack_bf16x2(f.z, f.w);
        float h0 = __uint_as_float(h01 << 16);
        float h1 = __uint_as_float(h01 & 0xffff0000u);
        float h2 = __uint_as_float(h23 << 16);
        float h3 = __uint_as_float(h23 & 0xffff0000u);
        uint32_t l01 = pack_bf16x2(f.x - h0, f.y - h1);
        uint32_t l23 = pack_bf16x2(f.z - h2, f.w - h3);
        uint32_t addr = bufbase + (uint32_t)k * 256u + colsw;
        sts64(addr, h01, h23);
        sts64(addr + 32768, l01, l23);
    }
}

__global__ __launch_bounds__(THREADS, 1)
void fused_kernel(const float* __restrict__ x,
                  const float* __restrict__ att,
                  const float* __restrict__ b,
                  float* __restrict__ out)
{
    extern __shared__ __align__(16) char smem[];
    const uint32_t sbase = smem_u32(smem);
    const int tid  = threadIdx.x;
    const int lane = tid & 31;
    const int wid  = tid >> 5;

    // --- load W once (64KB) ---
    {
        const float4* Wv = (const float4*)g_Wsw;
        float4* sWv = (float4*)(smem + SM_W);
#pragma unroll
        for (int i = 0; i < 8; i++)
            sWv[tid + THREADS * i] = Wv[tid + THREADS * i];
    }

    // --- warp-tile constants ---
    const int ocb = (wid & 3) * 32;          // oc group
    const int vh  = (wid >> 2) * 32;         // vox group (0..3)
    const int ocl = ocb + (lane >> 2);

    // A-side ldmatrix (row-major [oc][k], verified R4/R5)
    const int aRow = ocb + (lane & 15);
    const uint32_t aSw = (uint32_t)((aRow & 7) << 4);
    const uint32_t aK  = (uint32_t)((lane >> 4) * 16);
    const uint32_t aB  = sbase + SM_W + (uint32_t)aRow * 256u;

    // B-side ldmatrix.trans ([k][vox]): lanes 0-15 k=lane, n=vh+nbp*16;
    //                                   lanes 16-31 k=lane-16, n=+8
    const int bK = lane & 15;
    uint32_t bOffBase[2];
#pragma unroll
    for (int nbp = 0; nbp < 2; nbp++) {
        uint32_t col = (uint32_t)((vh + nbp * 16 + ((lane >> 4) * 8)) * 2);
        bOffBase[nbp] = (uint32_t)bK * 256u + (col ^ ((uint32_t)(bK & 7) << 4));
    }

    const float bias0a = __ldg(b + ocl);
    const float bias0b = __ldg(b + ocl + 8);
    const float bias1a = __ldg(b + ocl + 16);
    const float bias1b = __ldg(b + ocl + 24);

    // --- prologue: load tile0 ---
    int t = blockIdx.x;
    {
        XFrag r0;
        ldg_tile(x, t * TILE_V, wid, lane, r0);
        sts_tile(sbase, wid, lane, r0);
    }
    __syncthreads();

    int cur = 0;
    while (true) {
        const int tn = t + GRID;
        const bool has_next = (tn < NTILES);

        // prefetch next tile (latency hidden under MMA)
        XFrag rn;
        if (has_next) ldg_tile(x, tn * TILE_V, wid, lane, rn);

        // --- accumulators, init with bias ---
        float acc[2][4][4];
#pragma unroll
        for (int nb = 0; nb < 4; nb++) {
            acc[0][nb][0] = bias0a; acc[0][nb][1] = bias0a;
            acc[0][nb][2] = bias0b; acc[0][nb][3] = bias0b;
            acc[1][nb][0] = bias1a; acc[1][nb][1] = bias1a;
            acc[1][nb][2] = bias1b; acc[1][nb][3] = bias1b;
        }

        // --- MMA over 8 k-steps, 3 split terms ---
        const uint32_t bufH = sbase + (uint32_t)cur * 65536u;
        const uint32_t bufL = bufH + 32768u;
#pragma unroll
        for (int ks = 0; ks < 8; ks++) {
            const uint32_t kbA = ((uint32_t)(ks * 32) + aK) ^ aSw;
            uint32_t a0h[4], a1h[4], a0l[4], a1l[4];
            ldsm_x4(aB + kbA,                a0h);
            ldsm_x4(aB + 4096 + kbA,         a1h);
            ldsm_x4(aB + 32768 + kbA,        a0l);
            ldsm_x4(aB + 32768 + 4096 + kbA, a1l);

            const uint32_t krow = (uint32_t)(ks * 4096);
#pragma unroll
            for (int nbp = 0; nbp < 2; nbp++) {
                uint32_t bh[4], bl[4];
                ldsm_x4_t(bufH + krow + bOffBase[nbp], bh);
                ldsm_x4_t(bufL + krow + bOffBase[nbp], bl);
                mma16816(acc[0][2 * nbp],     a0h, bh[0], bh[1]);
                mma16816(acc[1][2 * nbp],     a1h, bh[0], bh[1]);
                mma16816(acc[0][2 * nbp],     a0h, bl[0], bl[1]);
                mma16816(acc[1][2 * nbp],     a1h, bl[0], bl[1]);
                mma16816(acc[0][2 * nbp],     a0l, bh[0], bh[1]);
                mma16816(acc[1][2 * nbp],     a1l, bh[0], bh[1]);
                mma16816(acc[0][2 * nbp + 1], a0h, bh[2], bh[3]);
                mma16816(acc[1][2 * nbp + 1], a1h, bh[2], bh[3]);
                mma16816(acc[0][2 * nbp + 1], a0h, bl[2], bl[3]);
                mma16816(acc[1][2 * nbp + 1], a1h, bl[2], bl[3]);
                mma16816(acc[0][2 * nbp + 1], a0l, bh[2], bh[3]);
                mma16816(acc[1][2 * nbp + 1], a1l, bh[2], bh[3]);
            }
        }

        // store next tile into the other buffer, then barrier
        if (has_next) sts_tile(sbase + (uint32_t)(cur ^ 1) * 65536u, wid, lane, rn);
        __syncthreads();

        // --- epilogue for tile t (regs + gmem only) ---
        const int voxbase = t * TILE_V + vh + 2 * (lane & 3);
#pragma unroll
        for (int tt = 0; tt < 2; tt++) {
            const int oc0 = ocl + 16 * tt;
            const int oc1 = oc0 + 8;
            const float* att0 = att + (size_t)oc0 * (LPATCH * PPSQ);
            const float* att1 = att + (size_t)oc1 * (LPATCH * PPSQ);
            const float* inz0 = g_invnz + oc0 * LPATCH;
            const float* inz1 = g_invnz + oc1 * LPATCH;
            float* o0 = out + (size_t)oc0 * NVOX;
            float* o1 = out + (size_t)oc1 * NVOX;
#pragma unroll
            for (int nb = 0; nb < 4; nb++) {
                const int v = voxbase + nb * 8;   // even; v,v+1 same d-plane
                int d  = v / HWDIM;
                int hw = v - d * HWDIM;
                int id = d / PATCH,  pd = d  - id * PATCH;
                int iw = hw / PATCH, pw = hw - iw * PATCH;
                int l0 = id * NW + iw, p0 = pd * PATCH + pw;
                int l1, p1;
                if (pw == PATCH - 1) { l1 = l0 + 1; p1 = pd * PATCH; }
                else                 { l1 = l0;     p1 = p0 + 1; }

                float a00 = att0[(size_t)l0 * PPSQ + p0] * inz0[l0];
                float a01 = att0[(size_t)l1 * PPSQ + p1] * inz0[l1];
                float a10 = att1[(size_t)l0 * PPSQ + p0] * inz1[l0];
                float a11 = att1[(size_t)l1 * PPSQ + p1] * inz1[l1];

                float y;
                float2 r;
                y = acc[tt][nb][0]; r.x = y * (y + a00 + 1.0f);
                r.x = (r.x >= 0.0f) ? r.x : 0.2f * r.x;
                y = acc[tt][nb][1]; r.y = y * (y + a01 + 1.0f);
                r.y = (r.y >= 0.0f) ? r.y : 0.2f * r.y;
                *(float2*)(o0 + v) = r;

                y = acc[tt][nb][2]; r.x = y * (y + a10 + 1.0f);
                r.x = (r.x >= 0.0f) ? r.x : 0.2f * r.x;
                y = acc[tt][nb][3]; r.y = y * (y + a11 + 1.0f);
                r.y = (r.y >= 0.0f) ? r.y : 0.2f * r.y;
                *(float2*)(o1 + v) = r;
            }
        }

        if (!has_next) break;
        t = tn;
        cur ^= 1;
    }
}

// ---------------------------------------------------------------------------
extern "C" void kernel_launch(void* const* d_in, const int* in_sizes, int n_in,
                              void* d_out, int out_size)
{
    (void)in_sizes; (void)n_in; (void)out_size;
    const float* x   = (const float*)d_in[0];
    const float* att = (const float*)d_in[1];
    const float* W   = (const float*)d_in[2];
    const float* b   = (const float*)d_in[3];
    float* out = (float*)d_out;

    prep_kernel<<<9216, 256>>>(att, W);

    cudaFuncSetAttribute(fused_kernel,
                         cudaFuncAttributeMaxDynamicSharedMemorySize,
                         SMEM_TOTAL);
    fused_kernel<<<GRID, THREADS, SMEM_TOTAL>>>(x, att, b, out);
}

// round 7
// speedup vs baseline: 1.6508x; 1.3297x over previous
#include <cuda_runtime.h>
#include <cuda_bf16.h>
#include <cstdint>

// ---------------------------------------------------------------------------
//   y   = W @ x + b   (oc=128, cin=128, vox=186624)
//   out = leaky_0.2( y * (y + att[c,l,pp]/nz[c,l] + 1) )
// GEMM on mma.sync m16n8k16 (bf16) via 3-way split: Wh*xh + Wh*xl + Wl*xh
// R7: prep pre-scales att -> bf16 (kills invnz from hot loop);
//     fused prefetches epilogue att into regs before MMA; MMA acc interleave.
// ---------------------------------------------------------------------------

#define CIN    128
#define COUT   128
#define HWDIM  5184
#define NVOX   186624
#define PATCH  9
#define PPSQ   81
#define NW     576
#define LPATCH 2304

#define TILE_V  128
#define NTILES  1458          // NVOX / TILE_V
#define GRID    148
#define THREADS 512

// dynamic smem (bytes): buf0 xh+xl (64KB) @0, buf1 @65536, W @131072 (64KB)
#define SM_W  131072
#define SMEM_TOTAL 196608

__device__ __align__(16) unsigned short g_Wsw[32768];   // [Wh][Wl], swizzled
__device__ __align__(16) unsigned short g_atts[COUT * LPATCH * PPSQ]; // bf16 att/nz

// ---------------------------------------------------------------------------
// helpers
// ---------------------------------------------------------------------------
__device__ __forceinline__ uint32_t smem_u32(const void* p) {
    uint32_t a;
    asm("{ .reg .u64 t; cvta.to.shared.u64 t, %1; cvt.u32.u64 %0, t; }"
        : "=r"(a) : "l"(p));
    return a;
}
__device__ __forceinline__ uint32_t pack_bf16x2(float lo, float hi) {
    uint32_t r;
    asm("cvt.rn.bf16x2.f32 %0, %1, %2;" : "=r"(r) : "f"(hi), "f"(lo));
    return r;
}
__device__ __forceinline__ int redux_add(int v) {
    int r;
    asm("redux.sync.add.s32 %0, %1, 0xffffffff;" : "=r"(r) : "r"(v));
    return r;
}
__device__ __forceinline__ void sts64(uint32_t addr, uint32_t a, uint32_t b) {
    asm volatile("st.shared.v2.u32 [%0], {%1, %2};"
                 :: "r"(addr), "r"(a), "r"(b) : "memory");
}
__device__ __forceinline__ void ldsm_x4(uint32_t addr, uint32_t* r) {
    asm volatile("ldmatrix.sync.aligned.m8n8.x4.shared.b16 {%0,%1,%2,%3}, [%4];"
                 : "=r"(r[0]), "=r"(r[1]), "=r"(r[2]), "=r"(r[3]) : "r"(addr));
}
__device__ __forceinline__ void ldsm_x4_t(uint32_t addr, uint32_t* r) {
    asm volatile("ldmatrix.sync.aligned.m8n8.x4.trans.shared.b16 {%0,%1,%2,%3}, [%4];"
                 : "=r"(r[0]), "=r"(r[1]), "=r"(r[2]), "=r"(r[3]) : "r"(addr));
}
__device__ __forceinline__ void mma16816(float* d, const uint32_t* a,
                                         uint32_t b0, uint32_t b1) {
    asm volatile(
        "mma.sync.aligned.m16n8k16.row.col.f32.bf16.bf16.f32 "
        "{%0,%1,%2,%3}, {%4,%5,%6,%7}, {%8,%9}, {%0,%1,%2,%3};"
        : "+f"(d[0]), "+f"(d[1]), "+f"(d[2]), "+f"(d[3])
        : "r"(a[0]), "r"(a[1]), "r"(a[2]), "r"(a[3]), "r"(b0), "r"(b1));
}
__device__ __forceinline__ unsigned short ldg_u16(const unsigned short* p) {
    unsigned short v;
    asm volatile("ld.global.nc.u16 %0, [%1];" : "=h"(v) : "l"(p));
    return v;
}
__device__ __forceinline__ float bf2f(unsigned short v) {
    return __uint_as_float((uint32_t)v << 16);
}
__device__ __forceinline__ float sel4(int r, float a, float b, float c, float d) {
    float v = a;
    v = (r == 1) ? b : v;
    v = (r == 2) ? c : v;
    v = (r == 3) ? d : v;
    return v;
}
// swizzled byte offset in a 256B-row tile, 16B-chunk xor by (row&7)
__device__ __forceinline__ uint32_t swz(int row, uint32_t colbyte) {
    return (uint32_t)row * 256u + (colbyte ^ (uint32_t)((row & 7) << 4));
}

// ---------------------------------------------------------------------------
// Prep: W bf16 hi/lo split (swizzled) + att -> bf16(att/nz) into g_atts.
// Warp handles 2 groups of 4 rows (6 independent LDG.128 in flight).
// ---------------------------------------------------------------------------
__device__ __forceinline__ void process_group(const float4* f, int g, int lane)
{
    int c0 = 0, c1 = 0, c2 = 0, c3 = 0;
#pragma unroll
    for (int p = 0; p < 3; p++) {
        int idx = p * 32 + lane;
        if (idx < 81) {
            float4 q = f[p];
            int e = idx * 4;
            int r0 = (e >= 81) + (e >= 162) + (e >= 243);
            int r3 = (e + 3 >= 81) + (e + 3 >= 162) + (e + 3 >= 243);
            if (r0 == r3) {
                int cnt = (q.x != 0.f) + (q.y != 0.f) + (q.z != 0.f) + (q.w != 0.f);
                c0 += (r0 == 0) ? cnt : 0;
                c1 += (r0 == 1) ? cnt : 0;
                c2 += (r0 == 2) ? cnt : 0;
                c3 += (r0 == 3) ? cnt : 0;
            } else {
                float vv[4] = { q.x, q.y, q.z, q.w };
#pragma unroll
                for (int j = 0; j < 4; j++) {
                    int ej = e + j;
                    int rj = (ej >= 81) + (ej >= 162) + (ej >= 243);
                    int nz = (vv[j] != 0.f);
                    c0 += (rj == 0) ? nz : 0;
                    c1 += (rj == 1) ? nz : 0;
                    c2 += (rj == 2) ? nz : 0;
                    c3 += (rj == 3) ? nz : 0;
                }
            }
        }
    }
    c0 = redux_add(c0); c1 = redux_add(c1);
    c2 = redux_add(c2); c3 = redux_add(c3);
    float i0 = 1.0f / ((float)c0 + 1e-5f);
    float i1 = 1.0f / ((float)c1 + 1e-5f);
    float i2 = 1.0f / ((float)c2 + 1e-5f);
    float i3 = 1.0f / ((float)c3 + 1e-5f);

    // scale + store bf16
#pragma unroll
    for (int p = 0; p < 3; p++) {
        int idx = p * 32 + lane;
        if (idx < 81) {
            float4 q = f[p];
            int e = idx * 4;
            int r0 = (e >= 81) + (e >= 162) + (e >= 243);
            int r1 = (e + 1 >= 81) + (e + 1 >= 162) + (e + 1 >= 243);
            int r2 = (e + 2 >= 81) + (e + 2 >= 162) + (e + 2 >= 243);
            int r3 = (e + 3 >= 81) + (e + 3 >= 162) + (e + 3 >= 243);
            float s0 = sel4(r0, i0, i1, i2, i3);
            float s1 = sel4(r1, i0, i1, i2, i3);
            float s2 = sel4(r2, i0, i1, i2, i3);
            float s3 = sel4(r3, i0, i1, i2, i3);
            uint32_t u01 = pack_bf16x2(q.x * s0, q.y * s1);
            uint32_t u23 = pack_bf16x2(q.z * s2, q.w * s3);
            *(uint2*)(g_atts + (size_t)g * 324 + idx * 4) = make_uint2(u01, u23);
        }
    }
}

__global__ __launch_bounds__(256) void prep_kernel(const float* __restrict__ att,
                                                   const float* __restrict__ W)
{
    const int tid = threadIdx.x;
    const int blk = blockIdx.x;

    if (blk < 64) {   // W split: 16384 elements
        int idx = blk * 256 + tid;
        int oc = idx >> 7, k = idx & 127;
        float w = W[idx];
        __nv_bfloat16 h = __float2bfloat16(w);
        float hf = __bfloat162float(h);
        __nv_bfloat16 l = __float2bfloat16(w - hf);
        uint32_t off = swz(oc, (uint32_t)(k * 2)) >> 1;
        g_Wsw[off]         = *(unsigned short*)&h;
        g_Wsw[off + 16384] = *(unsigned short*)&l;
    }

    const int wg = (blk * 256 + tid) >> 5;   // warp id: 0..36863
    const int lane = tid & 31;
    const int g0 = wg * 2;                    // two 4-row groups per warp
    const float4* a4a = (const float4*)att + (size_t)g0 * 81;
    const float4* a4b = a4a + 81;

    float4 fa[3], fb[3];
#pragma unroll
    for (int p = 0; p < 3; p++) {
        int idx = p * 32 + lane;
        if (idx < 81) {
            fa[p] = __ldg(a4a + idx);
            fb[p] = __ldg(a4b + idx);
        }
    }
    process_group(fa, g0, lane);
    process_group(fb, g0 + 1, lane);
}

// ---------------------------------------------------------------------------
// Fused persistent kernel.
// ---------------------------------------------------------------------------
struct XFrag { float4 f[8]; };

__device__ __forceinline__ void ldg_tile(const float* __restrict__ x,
                                         int v0, int wid, int lane, XFrag& r)
{
    const float* xp = x + (size_t)wid * NVOX + v0 + lane * 4;
#pragma unroll
    for (int i = 0; i < 8; i++)
        r.f[i] = *(const float4*)(xp + (size_t)(16 * i) * NVOX);
}

__device__ __forceinline__ void sts_tile(uint32_t bufbase, int wid, int lane,
                                         const XFrag& r)
{
    const uint32_t colsw = ((uint32_t)(lane * 8)) ^ ((uint32_t)((wid & 7) << 4));
#pragma unroll
    for (int i = 0; i < 8; i++) {
        const int k = wid + 16 * i;
        float4 f = r.f[i];
        uint32_t h01 = pack_bf16x2(f.x, f.y);
        uint32_t h23 = pack_bf16x2(f.z, f.w);
        float h0 = __uint_as_float(h01 << 16);
        float h1 = __uint_as_float(h01 & 0xffff0000u);
        float h2 = __uint_as_float(h23 << 16);
        float h3 = __uint_as_float(h23 & 0xffff0000u);
        uint32_t l01 = pack_bf16x2(f.x - h0, f.y - h1);
        uint32_t l23 = pack_bf16x2(f.z - h2, f.w - h3);
        uint32_t addr = bufbase + (uint32_t)k * 256u + colsw;
        sts64(addr, h01, h23);
        sts64(addr + 32768, l01, l23);
    }
}

__global__ __launch_bounds__(THREADS, 1)
void fused_kernel(const float* __restrict__ x,
                  const float* __restrict__ b,
                  float* __restrict__ out)
{
    extern __shared__ __align__(16) char smem[];
    const uint32_t sbase = smem_u32(smem);
    const int tid  = threadIdx.x;
    const int lane = tid & 31;
    const int wid  = tid >> 5;

    // load W once (64KB)
    {
        const float4* Wv = (const float4*)g_Wsw;
        float4* sWv = (float4*)(smem + SM_W);
#pragma unroll
        for (int i = 0; i < 8; i++)
            sWv[tid + THREADS * i] = Wv[tid + THREADS * i];
    }

    const int ocb = (wid & 3) * 32;
    const int vh  = (wid >> 2) * 32;
    const int ocl = ocb + (lane >> 2);

    // A-side ldmatrix ([oc][k] row-major, verified)
    const int aRow = ocb + (lane & 15);
    const uint32_t aSw = (uint32_t)((aRow & 7) << 4);
    const uint32_t aK  = (uint32_t)((lane >> 4) * 16);
    const uint32_t aB  = sbase + SM_W + (uint32_t)aRow * 256u;

    // B-side ldmatrix.trans ([k][vox], verified)
    const int bK = lane & 15;
    uint32_t bOffBase[2];
#pragma unroll
    for (int nbp = 0; nbp < 2; nbp++) {
        uint32_t col = (uint32_t)((vh + nbp * 16 + ((lane >> 4) * 8)) * 2);
        bOffBase[nbp] = (uint32_t)bK * 256u + (col ^ ((uint32_t)(bK & 7) << 4));
    }

    const float bias0a = __ldg(b + ocl);
    const float bias0b = __ldg(b + ocl + 8);
    const float bias1a = __ldg(b + ocl + 16);
    const float bias1b = __ldg(b + ocl + 24);

    // prologue: tile0 into buf0
    int t = blockIdx.x;
    {
        XFrag r0;
        ldg_tile(x, t * TILE_V, wid, lane, r0);
        sts_tile(sbase, wid, lane, r0);
    }
    __syncthreads();

    int cur = 0;
    while (true) {
        const int tn = t + GRID;
        const bool has_next = (tn < NTILES);

        // prefetch next x tile into regs (latency hidden under MMA)
        XFrag rn;
        if (has_next) ldg_tile(x, tn * TILE_V, wid, lane, rn);

        // prefetch epilogue att values for tile t (volatile -> issue pre-MMA)
        unsigned short avr[2][4][4];
        {
            int l0x[4], p0x[4], l1x[4], p1x[4];
#pragma unroll
            for (int nb = 0; nb < 4; nb++) {
                int v  = t * TILE_V + vh + 2 * (lane & 3) + nb * 8;
                int d  = v / HWDIM;
                int hw = v - d * HWDIM;
                int id = d / PATCH,  pd = d  - id * PATCH;
                int iw = hw / PATCH, pw = hw - iw * PATCH;
                int l0 = id * NW + iw, p0 = pd * PATCH + pw;
                l0x[nb] = l0; p0x[nb] = p0;
                if (pw == PATCH - 1) { l1x[nb] = l0 + 1; p1x[nb] = pd * PATCH; }
                else                 { l1x[nb] = l0;     p1x[nb] = p0 + 1; }
            }
#pragma unroll
            for (int tt = 0; tt < 2; tt++) {
                const unsigned short* A0 =
                    g_atts + (size_t)(ocl + 16 * tt) * (LPATCH * PPSQ);
                const unsigned short* A1 = A0 + (size_t)8 * (LPATCH * PPSQ);
#pragma unroll
                for (int nb = 0; nb < 4; nb++) {
                    avr[tt][nb][0] = ldg_u16(A0 + l0x[nb] * PPSQ + p0x[nb]);
                    avr[tt][nb][1] = ldg_u16(A0 + l1x[nb] * PPSQ + p1x[nb]);
                    avr[tt][nb][2] = ldg_u16(A1 + l0x[nb] * PPSQ + p0x[nb]);
                    avr[tt][nb][3] = ldg_u16(A1 + l1x[nb] * PPSQ + p1x[nb]);
                }
            }
        }

        // accumulators, init with bias
        float acc[2][4][4];
#pragma unroll
        for (int nb = 0; nb < 4; nb++) {
            acc[0][nb][0] = bias0a; acc[0][nb][1] = bias0a;
            acc[0][nb][2] = bias0b; acc[0][nb][3] = bias0b;
            acc[1][nb][0] = bias1a; acc[1][nb][1] = bias1a;
            acc[1][nb][2] = bias1b; acc[1][nb][3] = bias1b;
        }

        // MMA over 8 k-steps, 3 split terms, 4-wide acc interleave
        const uint32_t bufH = sbase + (uint32_t)cur * 65536u;
        const uint32_t bufL = bufH + 32768u;
#pragma unroll
        for (int ks = 0; ks < 8; ks++) {
            const uint32_t kbA = ((uint32_t)(ks * 32) + aK) ^ aSw;
            uint32_t a0h[4], a1h[4], a0l[4], a1l[4];
            ldsm_x4(aB + kbA,                a0h);
            ldsm_x4(aB + 4096 + kbA,         a1h);
            ldsm_x4(aB + 32768 + kbA,        a0l);
            ldsm_x4(aB + 32768 + 4096 + kbA, a1l);

            const uint32_t krow = (uint32_t)(ks * 4096);
#pragma unroll
            for (int nbp = 0; nbp < 2; nbp++) {
                uint32_t bh[4], bl[4];
                ldsm_x4_t(bufH + krow + bOffBase[nbp], bh);
                ldsm_x4_t(bufL + krow + bOffBase[nbp], bl);
                float* A00 = acc[0][2 * nbp];
                float* A10 = acc[1][2 * nbp];
                float* A01 = acc[0][2 * nbp + 1];
                float* A11 = acc[1][2 * nbp + 1];
                mma16816(A00, a0h, bh[0], bh[1]);
                mma16816(A10, a1h, bh[0], bh[1]);
                mma16816(A01, a0h, bh[2], bh[3]);
                mma16816(A11, a1h, bh[2], bh[3]);
                mma16816(A00, a0h, bl[0], bl[1]);
                mma16816(A10, a1h, bl[0], bl[1]);
                mma16816(A01, a0h, bl[2], bl[3]);
                mma16816(A11, a1h, bl[2], bl[3]);
                mma16816(A00, a0l, bh[0], bh[1]);
                mma16816(A10, a1l, bh[0], bh[1]);
                mma16816(A01, a0l, bh[2], bh[3]);
                mma16816(A11, a1l, bh[2], bh[3]);
            }
        }

        // store next tile, then barrier
        if (has_next) sts_tile(sbase + (uint32_t)(cur ^ 1) * 65536u, wid, lane, rn);
        __syncthreads();

        // epilogue: regs + STG only
        const int voxbase = t * TILE_V + vh + 2 * (lane & 3);
#pragma unroll
        for (int tt = 0; tt < 2; tt++) {
            float* o0 = out + (size_t)(ocl + 16 * tt) * NVOX;
            float* o1 = o0 + (size_t)8 * NVOX;
#pragma unroll
            for (int nb = 0; nb < 4; nb++) {
                const int v = voxbase + nb * 8;
                float a00 = bf2f(avr[tt][nb][0]);
                float a01 = bf2f(avr[tt][nb][1]);
                float a10 = bf2f(avr[tt][nb][2]);
                float a11 = bf2f(avr[tt][nb][3]);

                float y;
                float2 r;
                y = acc[tt][nb][0]; r.x = y * (y + a00 + 1.0f);
                r.x = (r.x >= 0.0f) ? r.x : 0.2f * r.x;
                y = acc[tt][nb][1]; r.y = y * (y + a01 + 1.0f);
                r.y = (r.y >= 0.0f) ? r.y : 0.2f * r.y;
                *(float2*)(o0 + v) = r;

                y = acc[tt][nb][2]; r.x = y * (y + a10 + 1.0f);
                r.x = (r.x >= 0.0f) ? r.x : 0.2f * r.x;
                y = acc[tt][nb][3]; r.y = y * (y + a11 + 1.0f);
                r.y = (r.y >= 0.0f) ? r.y : 0.2f * r.y;
                *(float2*)(o1 + v) = r;
            }
        }

        if (!has_next) break;
        t = tn;
        cur ^= 1;
    }
}

// ---------------------------------------------------------------------------
extern "C" void kernel_launch(void* const* d_in, const int* in_sizes, int n_in,
                              void* d_out, int out_size)
{
    (void)in_sizes; (void)n_in; (void)out_size;
    const float* x   = (const float*)d_in[0];
    const float* att = (const float*)d_in[1];
    const float* W   = (const float*)d_in[2];
    const float* b   = (const float*)d_in[3];
    float* out = (float*)d_out;

    // 4608 CTAs x 8 warps x 2 groups x 4 rows = 294912 (c,l) rows
    prep_kernel<<<4608, 256>>>(att, W);

    cudaFuncSetAttribute(fused_kernel,
                         cudaFuncAttributeMaxDynamicSharedMemorySize,
                         SMEM_TOTAL);
    fused_kernel<<<GRID, THREADS, SMEM_TOTAL>>>(x, b, out);
}